// round 15
// baseline (speedup 1.0000x reference)
#include <cuda_runtime.h>
#include <cuda_fp16.h>
#include <cstdint>
#include <cstddef>

#define D_MODEL 1024
#define SEQ     2048
#define BATCH   2
#define NHEAD   16
#define HDIM    64
#define MTOT    (BATCH * SEQ)          // 4096 rows

// ---------------------------------------------------------------------------
// Scratch (no cudaMalloc allowed) — all single fp16
// ---------------------------------------------------------------------------
__device__ __half g_xh[MTOT * D_MODEL];
__device__ __half g_wh[4 * D_MODEL * D_MODEL];   // Wq|Wk|Wv|Wo rows contiguous
__device__ __half g_qh[MTOT * D_MODEL];
__device__ __half g_kh[MTOT * D_MODEL];
__device__ __half g_vh[MTOT * D_MODEL];
__device__ __half g_oh[MTOT * D_MODEL];

// ---------------------------------------------------------------------------
// PTX helpers (sm_100-safe)
// ---------------------------------------------------------------------------
__device__ __forceinline__ uint32_t smem_u32(const void* p) {
    uint32_t a;
    asm("{ .reg .u64 t; cvta.to.shared.u64 t, %1; cvt.u32.u64 %0, t; }" : "=r"(a) : "l"(p));
    return a;
}
#define CP16(dst, src) \
    asm volatile("cp.async.cg.shared.global [%0], [%1], 16;" :: "r"(dst), "l"(src))
#define CP_COMMIT() asm volatile("cp.async.commit_group;" ::: "memory")
#define CP_WAIT(n)  asm volatile("cp.async.wait_group %0;" :: "n"(n) : "memory")

#define LDSM4(r0, r1, r2, r3, addr) \
    asm volatile("ldmatrix.sync.aligned.m8n8.x4.shared.b16 {%0,%1,%2,%3}, [%4];" \
                 : "=r"(r0), "=r"(r1), "=r"(r2), "=r"(r3) : "r"(addr))
#define LDSM4T(r0, r1, r2, r3, addr) \
    asm volatile("ldmatrix.sync.aligned.m8n8.x4.trans.shared.b16 {%0,%1,%2,%3}, [%4];" \
                 : "=r"(r0), "=r"(r1), "=r"(r2), "=r"(r3) : "r"(addr))

#define MMA_F16(d, a, b0, b1) \
    asm volatile("mma.sync.aligned.m16n8k16.row.col.f32.f16.f16.f32 " \
                 "{%0,%1,%2,%3}, {%4,%5,%6,%7}, {%8,%9}, {%0,%1,%2,%3};" \
                 : "+f"((d)[0]), "+f"((d)[1]), "+f"((d)[2]), "+f"((d)[3]) \
                 : "r"((a)[0]), "r"((a)[1]), "r"((a)[2]), "r"((a)[3]), \
                   "r"(b0), "r"(b1))

__device__ __forceinline__ uint32_t pack2h(float a, float b) {
    __half2 h = __floats2half2_rn(a, b);
    return *(uint32_t*)&h;
}

// ---------------------------------------------------------------------------
// Preprocessing, split: prepA = x + Wq/Wk/Wv (needed by qkv);
//                       prepB = Wo only (needed by out). MLP=4.
// ---------------------------------------------------------------------------
#define N4X (MTOT * D_MODEL / 4)       // 1048576
#define N4W (D_MODEL * D_MODEL / 4)    // 262144 = 1<<18
#define WN  (D_MODEL * D_MODEL)
#define NPREPA (N4X + 3 * N4W)         // 1835008
#define PREPA_BLOCKS (NPREPA / (256 * 4))  // 1792
#define PREPB_BLOCKS (N4W / (256 * 4))     // 256

__global__ __launch_bounds__(256) void prepA_kernel(
    const float* __restrict__ x,
    const float* __restrict__ Wq, const float* __restrict__ Wk,
    const float* __restrict__ Wv,
    __half* __restrict__ xh, __half* __restrict__ wh)
{
    const int stride = PREPA_BLOCKS * 256;
#pragma unroll
    for (int rep = 0; rep < 4; rep++) {
        int i = blockIdx.x * 256 + threadIdx.x + rep * stride;
        const float* src;
        __half2* dst;
        int w;
        if (i < N4X) {
            src = x; dst = (__half2*)xh; w = i;
        } else {
            int t = i - N4X;
            int j = t >> 18;
            w = t & (N4W - 1);
            src = (j == 0) ? Wq : (j == 1) ? Wk : Wv;
            dst = (__half2*)(wh + (size_t)j * WN);
        }
        float4 v = ((const float4*)src)[w];
        dst[2 * w] = __floats2half2_rn(v.x, v.y);
        dst[2 * w + 1] = __floats2half2_rn(v.z, v.w);
    }
}

__global__ __launch_bounds__(256) void prepB_kernel(
    const float* __restrict__ Wo, __half* __restrict__ whO)
{
    const int stride = PREPB_BLOCKS * 256;
#pragma unroll
    for (int rep = 0; rep < 4; rep++) {
        int w = blockIdx.x * 256 + threadIdx.x + rep * stride;
        float4 v = ((const float4*)Wo)[w];
        __half2* dst = (__half2*)whO;
        dst[2 * w] = __floats2half2_rn(v.x, v.y);
        dst[2 * w + 1] = __floats2half2_rn(v.z, v.w);
    }
}

// ---------------------------------------------------------------------------
// GEMM core: 128x128 C tile, BK=64 chunks, K=1024 -> 16 chunks, single fp16.
// 3-stage cp.async ring, ONE __syncthreads per chunk. Hoisted addresses.
// ---------------------------------------------------------------------------
#define GK 1024
#define GLD 72                          // row stride in fp16 (144 B, conflict-free)
#define GTB  (128 * GLD * 2)            // 18432 B per matrix tile
#define GSTB (2 * GTB)                  // 36864 B per stage (A + B)
#define GEMM_SMEM (3 * GSTB)            // 110592 B -> 2 CTAs/SM
#define NCH 16

struct GemmCore {
    uint32_t smb;
    int lane, wr, wc;
    uint32_t dstA[4];
    uint32_t offA[4], offW[4];
    uint32_t aRow[4], bRow[2];
    float acc[4][4][4];

    __device__ __forceinline__ void init(uint32_t smb_, int tid, int bm, int bn) {
        smb = smb_;
        const int wid = tid >> 5;
        lane = tid & 31;
        wr = (wid & 1) * 64; wc = (wid >> 1) * 32;
#pragma unroll
        for (int it = 0; it < 4; it++) {
            int idx = tid + it * 256;
            int r = idx >> 3, u = idx & 7;
            dstA[it] = (uint32_t)(r * GLD) * 2 + u * 16;
            offA[it] = (uint32_t)(bm + r) * GK + u * 8;
            offW[it] = (uint32_t)(bn + r) * GK + u * 8;
        }
#pragma unroll
        for (int mt = 0; mt < 4; mt++)
            aRow[mt] = (uint32_t)((wr + mt * 16 + (lane & 15)) * GLD) * 2 + (lane >> 4) * 16;
#pragma unroll
        for (int ng = 0; ng < 2; ng++)
            bRow[ng] = GTB + (uint32_t)((wc + ng * 16 + (lane & 15)) * GLD) * 2 + (lane >> 4) * 16;
#pragma unroll
        for (int mt = 0; mt < 4; mt++)
#pragma unroll
            for (int j = 0; j < 4; j++)
#pragma unroll
                for (int r = 0; r < 4; r++) acc[mt][j][r] = 0.0f;
    }
    __device__ __forceinline__ void load_chunk(
        const __half* __restrict__ A, const __half* __restrict__ W,
        int c, int stg) {
        const __half* Ap = A + c * 64;
        const __half* Wp = W + c * 64;
        const uint32_t sa = smb + stg * GSTB;
#pragma unroll
        for (int it = 0; it < 4; it++)
            CP16(sa + dstA[it], Ap + offA[it]);
#pragma unroll
        for (int it = 0; it < 4; it++)
            CP16(sa + GTB + dstA[it], Wp + offW[it]);
    }
    __device__ __forceinline__ void compute(int stg) {
        const uint32_t sa = smb + stg * GSTB;
#pragma unroll
        for (int ks = 0; ks < 4; ks++) {
            const uint32_t colb = ks * 32;
            uint32_t a[4][4], b[2][4];
#pragma unroll
            for (int mt = 0; mt < 4; mt++)
                LDSM4(a[mt][0], a[mt][1], a[mt][2], a[mt][3], sa + aRow[mt] + colb);
#pragma unroll
            for (int ng = 0; ng < 2; ng++)
                LDSM4(b[ng][0], b[ng][1], b[ng][2], b[ng][3], sa + bRow[ng] + colb);
#pragma unroll
            for (int mt = 0; mt < 4; mt++)
#pragma unroll
                for (int j = 0; j < 4; j++)
                    MMA_F16(acc[mt][j], a[mt], b[j >> 1][j & 1], b[j >> 1][(j & 1) + 2]);
        }
    }
    __device__ __forceinline__ void run(
        const __half* __restrict__ A, const __half* __restrict__ W) {
        load_chunk(A, W, 0, 0); CP_COMMIT();
        load_chunk(A, W, 1, 1); CP_COMMIT();
        for (int c = 0; c < NCH; c++) {
            CP_WAIT(1);
            __syncthreads();
            if (c + 2 < NCH) load_chunk(A, W, c + 2, (c + 2) % 3);
            CP_COMMIT();
            compute(c % 3);
        }
    }
};

// ---------------------------------------------------------------------------
// QKV GEMM slice: one (batch, head-half). 12 N-tiles x 16 M-tiles = 192 CTAs.
// bx -> sec (Q/K/V) and column tile within the 512-col head-half.
// ---------------------------------------------------------------------------
__global__ __launch_bounds__(256, 2) void gemm_qkv(
    const __half* __restrict__ A, const __half* __restrict__ W,
    const float* __restrict__ bq, const float* __restrict__ bk,
    const float* __restrict__ bv,
    __half* __restrict__ Qh, __half* __restrict__ Kh, __half* __restrict__ Vh,
    int bm0, int hg)
{
    extern __shared__ __align__(128) char smg[];
    const int bx = blockIdx.x;                  // 0..11
    const int sec = bx >> 2;                    // 0:Q 1:K 2:V
    const int cb = hg * 512 + (bx & 3) * 128;   // column base in 1024-col matrix
    const int bn = sec * 1024 + cb;             // row base in fused weight
    const int bm = bm0 + blockIdx.y * 128;
    GemmCore g;
    g.init(smem_u32(smg), threadIdx.x, bm, bn);
    g.run(A, W);

    const float* bias = (sec == 0) ? bq : (sec == 1) ? bk : bv;
    __half* dst = (sec == 0) ? Qh : (sec == 1) ? Kh : Vh;
    const int rq = g.lane >> 2;
    const int cq = (g.lane & 3) * 2;
#pragma unroll
    for (int mt = 0; mt < 4; mt++) {
#pragma unroll
        for (int j = 0; j < 4; j++) {
            const int col = cb + g.wc + j * 8 + cq;
            const float b0 = bias[col], b1 = bias[col + 1];
            const int row0 = bm + g.wr + mt * 16 + rq;
            *(__half2*)(dst + (size_t)row0 * D_MODEL + col) =
                __floats2half2_rn(g.acc[mt][j][0] + b0, g.acc[mt][j][1] + b1);
            *(__half2*)(dst + (size_t)(row0 + 8) * D_MODEL + col) =
                __floats2half2_rn(g.acc[mt][j][2] + b0, g.acc[mt][j][3] + b1);
        }
    }
}

// ---------------------------------------------------------------------------
// Output projection GEMM (per batch): fp32 out + bias, N=1024.
// ---------------------------------------------------------------------------
__global__ __launch_bounds__(256, 2) void gemm_out(
    const __half* __restrict__ A, const __half* __restrict__ W,
    const float* __restrict__ bias, float* __restrict__ C, int bm0)
{
    extern __shared__ __align__(128) char smg[];
    const int bn = blockIdx.x * 128;
    const int bm = bm0 + blockIdx.y * 128;
    GemmCore g;
    g.init(smem_u32(smg), threadIdx.x, bm, bn);
    g.run(A, W);

    const int rq = g.lane >> 2;
    const int cq = (g.lane & 3) * 2;
#pragma unroll
    for (int mt = 0; mt < 4; mt++) {
#pragma unroll
        for (int j = 0; j < 4; j++) {
            const int col = bn + g.wc + j * 8 + cq;
            const float b0 = bias[col], b1 = bias[col + 1];
            const int row0 = bm + g.wr + mt * 16 + rq;
            *(float2*)(C + (size_t)row0 * D_MODEL + col) =
                make_float2(g.acc[mt][j][0] + b0, g.acc[mt][j][1] + b1);
            *(float2*)(C + (size_t)(row0 + 8) * D_MODEL + col) =
                make_float2(g.acc[mt][j][2] + b0, g.acc[mt][j][3] + b1);
        }
    }
}

// ---------------------------------------------------------------------------
// Flash attention slice (batch b, heads h0..h0+7). Paired Q tiles.
// Warp-level causal skip: warp wid skips key tiles fully masked for its rows
// (kt*64 > q0+wr+15) — provably identical output (masked tiles contribute 0).
// ---------------------------------------------------------------------------
#define ALD 72
#define AQ_B  (128 * ALD * 2)
#define AM_B  (64 * ALD * 2)
#define AST_B (2 * AM_B)
#define ATTN_SMEM (AQ_B + 3 * AST_B)   // 73728 B -> 2 CTAs/SM

#define SCL 0.18033688f                // 0.125 * log2(e)

__global__ __launch_bounds__(256, 2) void attn_mma(
    const __half* __restrict__ Qhp,
    const __half* __restrict__ Kh, const __half* __restrict__ Vh,
    __half* __restrict__ Oh, int b, int h0)
{
    extern __shared__ __align__(128) char smc[];
    const uint32_t smb = smem_u32(smc);
    const int tid = threadIdx.x;
    const int wid = tid >> 5;
    const int lane = tid & 31;
    const int bx = blockIdx.x;
    const int h = h0 + blockIdx.y;
    const size_t rc0 = (size_t)b * SEQ * D_MODEL + h * HDIM;

    const int wr = wid * 16;
    const uint32_t lrow = lane & 15;
    const uint32_t lc16 = (lane >> 4) * 16;

    auto load_q = [&](int q0) {
#pragma unroll
        for (int it = 0; it < 4; it++) {
            int idx = tid + it * 256;
            int r = idx >> 3, u = idx & 7;
            CP16(smb + (uint32_t)(r * ALD + u * 8) * 2,
                 Qhp + rc0 + (size_t)(q0 + r) * D_MODEL + u * 8);
        }
    };
    auto load_kv = [&](int kt, int stg) {
        const uint32_t sb = smb + AQ_B + stg * AST_B;
#pragma unroll
        for (int it = 0; it < 4; it++) {
            int t = tid + it * 256;
            int mtx = t >> 9;                   // 0:Kh 1:Vh
            int idx = t & 511, r = idx >> 3, u = idx & 7;
            const __half* src = (mtx == 0) ? Kh : Vh;
            CP16(sb + mtx * AM_B + (uint32_t)(r * ALD + u * 8) * 2,
                 src + rc0 + (size_t)(kt * 64 + r) * D_MODEL + u * 8);
        }
    };

    for (int half = 0; half < 2; half++) {
        const int qt = half ? (7 - bx) : (8 + bx);
        const int q0 = qt * 128;
        const int ktEnd = 2 * qt + 2;
        const int ktMaxW = (q0 + wr + 15) >> 6;   // last tile this warp needs

        float o[8][4];
#pragma unroll
        for (int nt = 0; nt < 8; nt++)
#pragma unroll
            for (int c = 0; c < 4; c++) o[nt][c] = 0.0f;
        float m0 = -1e30f, m1 = -1e30f, l0 = 0.0f, l1 = 0.0f;
        uint32_t qh[4][4];

        load_q(q0);
        load_kv(0, 0);
        CP_COMMIT();
        if (1 < ktEnd) load_kv(1, 1);
        CP_COMMIT();

        for (int kt = 0; kt < ktEnd; kt++) {
            CP_WAIT(1);
            __syncthreads();
            if (kt + 2 < ktEnd) load_kv(kt + 2, (kt + 2) % 3);
            CP_COMMIT();

            if (kt == 0) {
#pragma unroll
                for (int ks = 0; ks < 4; ks++) {
                    uint32_t a1 = smb + (uint32_t)((wr + lrow) * ALD) * 2 + ks * 32 + lc16;
                    LDSM4(qh[ks][0], qh[ks][1], qh[ks][2], qh[ks][3], a1);
                }
            }

            if (kt > ktMaxW) continue;   // fully masked for this warp's rows

            const uint32_t sb = smb + AQ_B + (kt % 3) * AST_B;

            // ---- S = Q K^T (single term) ----
            float s[8][4];
#pragma unroll
            for (int nt = 0; nt < 8; nt++)
#pragma unroll
                for (int c = 0; c < 4; c++) s[nt][c] = 0.0f;

#pragma unroll
            for (int ks = 0; ks < 4; ks++) {
                uint32_t kf[4][4];
#pragma unroll
                for (int ng = 0; ng < 4; ng++) {
                    uint32_t a1 = sb + (uint32_t)((ng * 16 + lrow) * ALD) * 2 + ks * 32 + lc16;
                    LDSM4(kf[ng][0], kf[ng][1], kf[ng][2], kf[ng][3], a1);
                }
#pragma unroll
                for (int nt = 0; nt < 8; nt++)
                    MMA_F16(s[nt], qh[ks], kf[nt >> 1][nt & 1], kf[nt >> 1][(nt & 1) + 2]);
            }

#pragma unroll
            for (int nt = 0; nt < 8; nt++)
#pragma unroll
                for (int c = 0; c < 4; c++) s[nt][c] *= SCL;   // log2-domain

            // ---- causal mask (diagonal tiles only) ----
            if (kt * 64 + 63 > q0 + wr) {
                const int r0 = q0 + wr + (lane >> 2);
#pragma unroll
                for (int nt = 0; nt < 8; nt++) {
                    const int c0 = kt * 64 + nt * 8 + 2 * (lane & 3);
                    if (c0 > r0)         s[nt][0] = -1e30f;
                    if (c0 + 1 > r0)     s[nt][1] = -1e30f;
                    if (c0 > r0 + 8)     s[nt][2] = -1e30f;
                    if (c0 + 1 > r0 + 8) s[nt][3] = -1e30f;
                }
            }

            // ---- online softmax (base-2, quad shuffles) ----
            float mx0 = -1e30f, mx1 = -1e30f;
#pragma unroll
            for (int nt = 0; nt < 8; nt++) {
                mx0 = fmaxf(mx0, fmaxf(s[nt][0], s[nt][1]));
                mx1 = fmaxf(mx1, fmaxf(s[nt][2], s[nt][3]));
            }
            mx0 = fmaxf(mx0, __shfl_xor_sync(0xffffffffu, mx0, 1));
            mx0 = fmaxf(mx0, __shfl_xor_sync(0xffffffffu, mx0, 2));
            mx1 = fmaxf(mx1, __shfl_xor_sync(0xffffffffu, mx1, 1));
            mx1 = fmaxf(mx1, __shfl_xor_sync(0xffffffffu, mx1, 2));
            const float n0 = fmaxf(m0, mx0), n1 = fmaxf(m1, mx1);
            const float cr0 = exp2f(m0 - n0), cr1 = exp2f(m1 - n1);
            m0 = n0; m1 = n1;
            float sum0 = 0.0f, sum1 = 0.0f;
#pragma unroll
            for (int nt = 0; nt < 8; nt++) {
                s[nt][0] = exp2f(s[nt][0] - n0); sum0 += s[nt][0];
                s[nt][1] = exp2f(s[nt][1] - n0); sum0 += s[nt][1];
                s[nt][2] = exp2f(s[nt][2] - n1); sum1 += s[nt][2];
                s[nt][3] = exp2f(s[nt][3] - n1); sum1 += s[nt][3];
            }
            sum0 += __shfl_xor_sync(0xffffffffu, sum0, 1);
            sum0 += __shfl_xor_sync(0xffffffffu, sum0, 2);
            sum1 += __shfl_xor_sync(0xffffffffu, sum1, 1);
            sum1 += __shfl_xor_sync(0xffffffffu, sum1, 2);
            l0 = l0 * cr0 + sum0;
            l1 = l1 * cr1 + sum1;
#pragma unroll
            for (int nt = 0; nt < 8; nt++) {
                o[nt][0] *= cr0; o[nt][1] *= cr0;
                o[nt][2] *= cr1; o[nt][3] *= cr1;
            }

            // ---- P fragments: single fp16 ----
            uint32_t ph[4][4];
#pragma unroll
            for (int ks = 0; ks < 4; ks++) {
                ph[ks][0] = pack2h(s[2 * ks][0], s[2 * ks][1]);
                ph[ks][1] = pack2h(s[2 * ks][2], s[2 * ks][3]);
                ph[ks][2] = pack2h(s[2 * ks + 1][0], s[2 * ks + 1][1]);
                ph[ks][3] = pack2h(s[2 * ks + 1][2], s[2 * ks + 1][3]);
            }

            // ---- O += P V (1 term) ----
#pragma unroll
            for (int ks = 0; ks < 4; ks++) {
                uint32_t vh[4][4];
#pragma unroll
                for (int ng = 0; ng < 4; ng++) {
                    uint32_t a1 = sb + AM_B + (uint32_t)((ks * 16 + lrow) * ALD) * 2 + ng * 32 + lc16;
                    LDSM4T(vh[ng][0], vh[ng][1], vh[ng][2], vh[ng][3], a1);
                }
#pragma unroll
                for (int nt = 0; nt < 8; nt++)
                    MMA_F16(o[nt], ph[ks], vh[nt >> 1][(nt & 1) * 2], vh[nt >> 1][(nt & 1) * 2 + 1]);
            }
        }

        // ---- epilogue: normalize, fp16 store ----
        const float i0 = 1.0f / l0, i1 = 1.0f / l1;
        const size_t r0 = (size_t)(b * SEQ + q0 + wr + (lane >> 2));
        const int colb = h * HDIM + 2 * (lane & 3);
#pragma unroll
        for (int nt = 0; nt < 8; nt++) {
            const int col = colb + nt * 8;
            *(uint32_t*)(Oh + r0 * D_MODEL + col) = pack2h(o[nt][0] * i0, o[nt][1] * i0);
            *(uint32_t*)(Oh + (r0 + 8) * D_MODEL + col) = pack2h(o[nt][2] * i1, o[nt][3] * i1);
        }

        // drain before next tile reuses Q/KV smem
        CP_WAIT(0);
        __syncthreads();
    }
}

// ---------------------------------------------------------------------------
// Launch: 4 pipelines (2 batches x 2 head-halves) on 4 streams, forked off
// prepA; Wo conversion on a side stream; outs join their batch's two slices.
// ---------------------------------------------------------------------------
extern "C" void kernel_launch(void* const* d_in, const int* in_sizes, int n_in,
                              void* d_out, int out_size)
{
    (void)in_sizes; (void)n_in; (void)out_size;
    const float* x  = (const float*)d_in[0];
    const float* Wq = (const float*)d_in[1];
    const float* bq = (const float*)d_in[2];
    const float* Wk = (const float*)d_in[3];
    const float* bk = (const float*)d_in[4];
    const float* Wv = (const float*)d_in[5];
    const float* bv = (const float*)d_in[6];
    const float* Wo = (const float*)d_in[7];
    const float* bo = (const float*)d_in[8];
    float* out = (float*)d_out;

    __half *xh, *wh, *qh, *kh, *vh, *oh;
    cudaGetSymbolAddress((void**)&xh, g_xh);
    cudaGetSymbolAddress((void**)&wh, g_wh);
    cudaGetSymbolAddress((void**)&qh, g_qh);
    cudaGetSymbolAddress((void**)&kh, g_kh);
    cudaGetSymbolAddress((void**)&vh, g_vh);
    cudaGetSymbolAddress((void**)&oh, g_oh);

    cudaFuncSetAttribute(attn_mma,
                         cudaFuncAttributeMaxDynamicSharedMemorySize, ATTN_SMEM);
    cudaFuncSetAttribute(gemm_qkv,
                         cudaFuncAttributeMaxDynamicSharedMemorySize, GEMM_SMEM);
    cudaFuncSetAttribute(gemm_out,
                         cudaFuncAttributeMaxDynamicSharedMemorySize, GEMM_SMEM);

    // One-time stream/event creation (first call = correctness run, not
    // under capture; later captures reuse them via fork/join events).
    static cudaStream_t s1 = nullptr, s2 = nullptr, s3 = nullptr;
    static cudaEvent_t eFork = nullptr, eWo = nullptr;
    static cudaEvent_t eA01 = nullptr, eA11 = nullptr, eOut1 = nullptr;
    static bool init_ok = false;
    if (!init_ok) {
        bool ok = true;
        ok = ok && (cudaStreamCreateWithFlags(&s1, cudaStreamNonBlocking) == cudaSuccess);
        ok = ok && (cudaStreamCreateWithFlags(&s2, cudaStreamNonBlocking) == cudaSuccess);
        ok = ok && (cudaStreamCreateWithFlags(&s3, cudaStreamNonBlocking) == cudaSuccess);
        ok = ok && (cudaEventCreateWithFlags(&eFork, cudaEventDisableTiming) == cudaSuccess);
        ok = ok && (cudaEventCreateWithFlags(&eWo, cudaEventDisableTiming) == cudaSuccess);
        ok = ok && (cudaEventCreateWithFlags(&eA01, cudaEventDisableTiming) == cudaSuccess);
        ok = ok && (cudaEventCreateWithFlags(&eA11, cudaEventDisableTiming) == cudaSuccess);
        ok = ok && (cudaEventCreateWithFlags(&eOut1, cudaEventDisableTiming) == cudaSuccess);
        init_ok = ok;
        if (!ok) { s1 = s2 = s3 = nullptr; }
    }

    const __half* whO = wh + (size_t)3 * WN;
    const dim3 gQKV(12, SEQ / 128);              // 192 CTAs per slice
    const dim3 gAttn(SEQ / 256, NHEAD / 2);      // (8, 8) per slice
    const dim3 gOut(D_MODEL / 128, SEQ / 128);   // (8, 16) per batch

    if (s1) {
        prepA_kernel<<<PREPA_BLOCKS, 256>>>(x, Wq, Wk, Wv, xh, wh);
        cudaEventRecord(eFork, 0);
        cudaStreamWaitEvent(s1, eFork, 0);
        cudaStreamWaitEvent(s2, eFork, 0);
        cudaStreamWaitEvent(s3, eFork, 0);

        // Wo conversion off critical path (s3, before its qkv slice)
        prepB_kernel<<<PREPB_BLOCKS, 256, 0, s3>>>(Wo, (__half*)whO);
        cudaEventRecord(eWo, s3);

        // qkv slices: (batch0,hg0) s0, (batch0,hg1) s1, (batch1,hg0) s2, (batch1,hg1) s3
        gemm_qkv<<<gQKV, 256, GEMM_SMEM, 0 >>>(xh, wh, bq, bk, bv, qh, kh, vh, 0,   0);
        gemm_qkv<<<gQKV, 256, GEMM_SMEM, s1>>>(xh, wh, bq, bk, bv, qh, kh, vh, 0,   1);
        gemm_qkv<<<gQKV, 256, GEMM_SMEM, s2>>>(xh, wh, bq, bk, bv, qh, kh, vh, SEQ, 0);
        gemm_qkv<<<gQKV, 256, GEMM_SMEM, s3>>>(xh, wh, bq, bk, bv, qh, kh, vh, SEQ, 1);

        // attn slices (same streams)
        attn_mma<<<gAttn, 256, ATTN_SMEM, 0 >>>(qh, kh, vh, oh, 0, 0);
        attn_mma<<<gAttn, 256, ATTN_SMEM, s1>>>(qh, kh, vh, oh, 0, 8);
        cudaEventRecord(eA01, s1);
        attn_mma<<<gAttn, 256, ATTN_SMEM, s2>>>(qh, kh, vh, oh, 1, 0);
        attn_mma<<<gAttn, 256, ATTN_SMEM, s3>>>(qh, kh, vh, oh, 1, 8);
        cudaEventRecord(eA11, s3);

        // out0 on s0: needs attn(0,hg1) + Wo
        cudaStreamWaitEvent(0, eA01, 0);
        cudaStreamWaitEvent(0, eWo, 0);
        gemm_out<<<gOut, 256, GEMM_SMEM, 0>>>(oh, whO, bo, out, 0);

        // out1 on s2: needs attn(1,hg1) + Wo
        cudaStreamWaitEvent(s2, eA11, 0);
        cudaStreamWaitEvent(s2, eWo, 0);
        gemm_out<<<gOut, 256, GEMM_SMEM, s2>>>(oh, whO, bo, out, SEQ);

        // join s2 back to capture stream
        cudaEventRecord(eOut1, s2);
        cudaStreamWaitEvent(0, eOut1, 0);
    } else {
        // fallback: serial on default stream
        prepA_kernel<<<PREPA_BLOCKS, 256>>>(x, Wq, Wk, Wv, xh, wh);
        prepB_kernel<<<PREPB_BLOCKS, 256>>>(Wo, (__half*)whO);
        gemm_qkv<<<gQKV, 256, GEMM_SMEM>>>(xh, wh, bq, bk, bv, qh, kh, vh, 0,   0);
        gemm_qkv<<<gQKV, 256, GEMM_SMEM>>>(xh, wh, bq, bk, bv, qh, kh, vh, 0,   1);
        gemm_qkv<<<gQKV, 256, GEMM_SMEM>>>(xh, wh, bq, bk, bv, qh, kh, vh, SEQ, 0);
        gemm_qkv<<<gQKV, 256, GEMM_SMEM>>>(xh, wh, bq, bk, bv, qh, kh, vh, SEQ, 1);
        attn_mma<<<gAttn, 256, ATTN_SMEM>>>(qh, kh, vh, oh, 0, 0);
        attn_mma<<<gAttn, 256, ATTN_SMEM>>>(qh, kh, vh, oh, 0, 8);
        attn_mma<<<gAttn, 256, ATTN_SMEM>>>(qh, kh, vh, oh, 1, 0);
        attn_mma<<<gAttn, 256, ATTN_SMEM>>>(qh, kh, vh, oh, 1, 8);
        gemm_out<<<gOut, 256, GEMM_SMEM>>>(oh, whO, bo, out, 0);
        gemm_out<<<gOut, 256, GEMM_SMEM>>>(oh, whO, bo, out, SEQ);
    }
}

// round 16
// speedup vs baseline: 1.0266x; 1.0266x over previous
#include <cuda_runtime.h>
#include <cuda_fp16.h>
#include <cstdint>
#include <cstddef>

#define D_MODEL 1024
#define SEQ     2048
#define BATCH   2
#define NHEAD   16
#define HDIM    64
#define MTOT    (BATCH * SEQ)          // 4096 rows

// ---------------------------------------------------------------------------
// Scratch (no cudaMalloc allowed) — all single fp16
// ---------------------------------------------------------------------------
__device__ __half g_xh[MTOT * D_MODEL];
__device__ __half g_wh[4 * D_MODEL * D_MODEL];   // Wq|Wk|Wv|Wo rows contiguous
__device__ __half g_qh[MTOT * D_MODEL];
__device__ __half g_kh[MTOT * D_MODEL];
__device__ __half g_vh[MTOT * D_MODEL];
__device__ __half g_oh[MTOT * D_MODEL];

// ---------------------------------------------------------------------------
// PTX helpers (sm_100-safe)
// ---------------------------------------------------------------------------
__device__ __forceinline__ uint32_t smem_u32(const void* p) {
    uint32_t a;
    asm("{ .reg .u64 t; cvta.to.shared.u64 t, %1; cvt.u32.u64 %0, t; }" : "=r"(a) : "l"(p));
    return a;
}
#define CP16(dst, src) \
    asm volatile("cp.async.cg.shared.global [%0], [%1], 16;" :: "r"(dst), "l"(src))
#define CP_COMMIT() asm volatile("cp.async.commit_group;" ::: "memory")
#define CP_WAIT(n)  asm volatile("cp.async.wait_group %0;" :: "n"(n) : "memory")

#define LDSM4(r0, r1, r2, r3, addr) \
    asm volatile("ldmatrix.sync.aligned.m8n8.x4.shared.b16 {%0,%1,%2,%3}, [%4];" \
                 : "=r"(r0), "=r"(r1), "=r"(r2), "=r"(r3) : "r"(addr))
#define LDSM4T(r0, r1, r2, r3, addr) \
    asm volatile("ldmatrix.sync.aligned.m8n8.x4.trans.shared.b16 {%0,%1,%2,%3}, [%4];" \
                 : "=r"(r0), "=r"(r1), "=r"(r2), "=r"(r3) : "r"(addr))

#define MMA_F16(d, a, b0, b1) \
    asm volatile("mma.sync.aligned.m16n8k16.row.col.f32.f16.f16.f32 " \
                 "{%0,%1,%2,%3}, {%4,%5,%6,%7}, {%8,%9}, {%0,%1,%2,%3};" \
                 : "+f"((d)[0]), "+f"((d)[1]), "+f"((d)[2]), "+f"((d)[3]) \
                 : "r"((a)[0]), "r"((a)[1]), "r"((a)[2]), "r"((a)[3]), \
                   "r"(b0), "r"(b1))

__device__ __forceinline__ uint32_t pack2h(float a, float b) {
    __half2 h = __floats2half2_rn(a, b);
    return *(uint32_t*)&h;
}

// ---------------------------------------------------------------------------
// Preprocessing: prepA = x + Wq/Wk/Wv (feeds qkv); prepB = Wo (feeds out).
// ---------------------------------------------------------------------------
#define N4X (MTOT * D_MODEL / 4)       // 1048576
#define N4W (D_MODEL * D_MODEL / 4)    // 262144 = 1<<18
#define WN  (D_MODEL * D_MODEL)
#define NPREPA (N4X + 3 * N4W)         // 1835008
#define PREPA_BLOCKS (NPREPA / (256 * 4))  // 1792
#define PREPB_BLOCKS (N4W / (256 * 4))     // 256

__global__ __launch_bounds__(256) void prepA_kernel(
    const float* __restrict__ x,
    const float* __restrict__ Wq, const float* __restrict__ Wk,
    const float* __restrict__ Wv,
    __half* __restrict__ xh, __half* __restrict__ wh)
{
    const int stride = PREPA_BLOCKS * 256;
#pragma unroll
    for (int rep = 0; rep < 4; rep++) {
        int i = blockIdx.x * 256 + threadIdx.x + rep * stride;
        const float* src;
        __half2* dst;
        int w;
        if (i < N4X) {
            src = x; dst = (__half2*)xh; w = i;
        } else {
            int t = i - N4X;
            int j = t >> 18;
            w = t & (N4W - 1);
            src = (j == 0) ? Wq : (j == 1) ? Wk : Wv;
            dst = (__half2*)(wh + (size_t)j * WN);
        }
        float4 v = ((const float4*)src)[w];
        dst[2 * w] = __floats2half2_rn(v.x, v.y);
        dst[2 * w + 1] = __floats2half2_rn(v.z, v.w);
    }
}

__global__ __launch_bounds__(256) void prepB_kernel(
    const float* __restrict__ Wo, __half* __restrict__ whO)
{
    const int stride = PREPB_BLOCKS * 256;
#pragma unroll
    for (int rep = 0; rep < 4; rep++) {
        int w = blockIdx.x * 256 + threadIdx.x + rep * stride;
        float4 v = ((const float4*)Wo)[w];
        __half2* dst = (__half2*)whO;
        dst[2 * w] = __floats2half2_rn(v.x, v.y);
        dst[2 * w + 1] = __floats2half2_rn(v.z, v.w);
    }
}

// ---------------------------------------------------------------------------
// GEMM core: 128x128 C tile, BK=64 chunks, K=1024 -> 16 chunks, single fp16.
// 3-stage cp.async ring, ONE __syncthreads per chunk. Hoisted addresses.
// ---------------------------------------------------------------------------
#define GK 1024
#define GLD 72                          // row stride in fp16 (144 B, conflict-free)
#define GTB  (128 * GLD * 2)            // 18432 B per matrix tile
#define GSTB (2 * GTB)                  // 36864 B per stage (A + B)
#define GEMM_SMEM (3 * GSTB)            // 110592 B -> 2 CTAs/SM
#define NCH 16

struct GemmCore {
    uint32_t smb;
    int lane, wr, wc;
    uint32_t dstA[4];
    uint32_t offA[4], offW[4];
    uint32_t aRow[4], bRow[2];
    float acc[4][4][4];

    __device__ __forceinline__ void init(uint32_t smb_, int tid, int bm, int bn) {
        smb = smb_;
        const int wid = tid >> 5;
        lane = tid & 31;
        wr = (wid & 1) * 64; wc = (wid >> 1) * 32;
#pragma unroll
        for (int it = 0; it < 4; it++) {
            int idx = tid + it * 256;
            int r = idx >> 3, u = idx & 7;
            dstA[it] = (uint32_t)(r * GLD) * 2 + u * 16;
            offA[it] = (uint32_t)(bm + r) * GK + u * 8;
            offW[it] = (uint32_t)(bn + r) * GK + u * 8;
        }
#pragma unroll
        for (int mt = 0; mt < 4; mt++)
            aRow[mt] = (uint32_t)((wr + mt * 16 + (lane & 15)) * GLD) * 2 + (lane >> 4) * 16;
#pragma unroll
        for (int ng = 0; ng < 2; ng++)
            bRow[ng] = GTB + (uint32_t)((wc + ng * 16 + (lane & 15)) * GLD) * 2 + (lane >> 4) * 16;
#pragma unroll
        for (int mt = 0; mt < 4; mt++)
#pragma unroll
            for (int j = 0; j < 4; j++)
#pragma unroll
                for (int r = 0; r < 4; r++) acc[mt][j][r] = 0.0f;
    }
    __device__ __forceinline__ void load_chunk(
        const __half* __restrict__ A, const __half* __restrict__ W,
        int c, int stg) {
        const __half* Ap = A + c * 64;
        const __half* Wp = W + c * 64;
        const uint32_t sa = smb + stg * GSTB;
#pragma unroll
        for (int it = 0; it < 4; it++)
            CP16(sa + dstA[it], Ap + offA[it]);
#pragma unroll
        for (int it = 0; it < 4; it++)
            CP16(sa + GTB + dstA[it], Wp + offW[it]);
    }
    __device__ __forceinline__ void compute(int stg) {
        const uint32_t sa = smb + stg * GSTB;
#pragma unroll
        for (int ks = 0; ks < 4; ks++) {
            const uint32_t colb = ks * 32;
            uint32_t a[4][4], b[2][4];
#pragma unroll
            for (int mt = 0; mt < 4; mt++)
                LDSM4(a[mt][0], a[mt][1], a[mt][2], a[mt][3], sa + aRow[mt] + colb);
#pragma unroll
            for (int ng = 0; ng < 2; ng++)
                LDSM4(b[ng][0], b[ng][1], b[ng][2], b[ng][3], sa + bRow[ng] + colb);
#pragma unroll
            for (int mt = 0; mt < 4; mt++)
#pragma unroll
                for (int j = 0; j < 4; j++)
                    MMA_F16(acc[mt][j], a[mt], b[j >> 1][j & 1], b[j >> 1][(j & 1) + 2]);
        }
    }
    __device__ __forceinline__ void run(
        const __half* __restrict__ A, const __half* __restrict__ W) {
        load_chunk(A, W, 0, 0); CP_COMMIT();
        load_chunk(A, W, 1, 1); CP_COMMIT();
        for (int c = 0; c < NCH; c++) {
            CP_WAIT(1);
            __syncthreads();
            if (c + 2 < NCH) load_chunk(A, W, c + 2, (c + 2) % 3);
            CP_COMMIT();
            compute(c % 3);
        }
    }
};

// ---------------------------------------------------------------------------
// Fused QKV GEMM (per batch): N=3072 over contiguous Wq|Wk|Wv. 384 CTAs.
// ---------------------------------------------------------------------------
__global__ __launch_bounds__(256, 2) void gemm_qkv(
    const __half* __restrict__ A, const __half* __restrict__ W,
    const float* __restrict__ bq, const float* __restrict__ bk,
    const float* __restrict__ bv,
    __half* __restrict__ Qh, __half* __restrict__ Kh, __half* __restrict__ Vh,
    int bm0)
{
    extern __shared__ __align__(128) char smg[];
    const int bn = blockIdx.x * 128;            // 0..2944
    const int bm = bm0 + blockIdx.y * 128;
    GemmCore g;
    g.init(smem_u32(smg), threadIdx.x, bm, bn);
    g.run(A, W);

    const int bh = bn >> 10;                    // 0:Q 1:K 2:V
    const int cb = bn & 1023;
    const float* bias = (bh == 0) ? bq : (bh == 1) ? bk : bv;
    __half* dst = (bh == 0) ? Qh : (bh == 1) ? Kh : Vh;
    const int rq = g.lane >> 2;
    const int cq = (g.lane & 3) * 2;
#pragma unroll
    for (int mt = 0; mt < 4; mt++) {
#pragma unroll
        for (int j = 0; j < 4; j++) {
            const int col = cb + g.wc + j * 8 + cq;
            const float b0 = bias[col], b1 = bias[col + 1];
            const int row0 = bm + g.wr + mt * 16 + rq;
            *(__half2*)(dst + (size_t)row0 * D_MODEL + col) =
                __floats2half2_rn(g.acc[mt][j][0] + b0, g.acc[mt][j][1] + b1);
            *(__half2*)(dst + (size_t)(row0 + 8) * D_MODEL + col) =
                __floats2half2_rn(g.acc[mt][j][2] + b0, g.acc[mt][j][3] + b1);
        }
    }
}

// ---------------------------------------------------------------------------
// Output projection GEMM (per batch): fp32 out + bias, N=1024.
// ---------------------------------------------------------------------------
__global__ __launch_bounds__(256, 2) void gemm_out(
    const __half* __restrict__ A, const __half* __restrict__ W,
    const float* __restrict__ bias, float* __restrict__ C, int bm0)
{
    extern __shared__ __align__(128) char smg[];
    const int bn = blockIdx.x * 128;
    const int bm = bm0 + blockIdx.y * 128;
    GemmCore g;
    g.init(smem_u32(smg), threadIdx.x, bm, bn);
    g.run(A, W);

    const int rq = g.lane >> 2;
    const int cq = (g.lane & 3) * 2;
#pragma unroll
    for (int mt = 0; mt < 4; mt++) {
#pragma unroll
        for (int j = 0; j < 4; j++) {
            const int col = bn + g.wc + j * 8 + cq;
            const float b0 = bias[col], b1 = bias[col + 1];
            const int row0 = bm + g.wr + mt * 16 + rq;
            *(float2*)(C + (size_t)row0 * D_MODEL + col) =
                make_float2(g.acc[mt][j][0] + b0, g.acc[mt][j][1] + b1);
            *(float2*)(C + (size_t)(row0 + 8) * D_MODEL + col) =
                make_float2(g.acc[mt][j][2] + b0, g.acc[mt][j][3] + b1);
        }
    }
}

// ---------------------------------------------------------------------------
// Flash attention (per batch, all 16 heads). Paired Q tiles, 3-stage KV ring.
// Warp-level causal skip: warp wid skips key tiles fully masked for its rows
// (kt*64 > q0+wr+15) — output bit-identical (masked tiles contribute 0).
// ---------------------------------------------------------------------------
#define ALD 72
#define AQ_B  (128 * ALD * 2)
#define AM_B  (64 * ALD * 2)
#define AST_B (2 * AM_B)
#define ATTN_SMEM (AQ_B + 3 * AST_B)   // 73728 B -> 2 CTAs/SM

#define SCL 0.18033688f                // 0.125 * log2(e)

__global__ __launch_bounds__(256, 2) void attn_mma(
    const __half* __restrict__ Qhp,
    const __half* __restrict__ Kh, const __half* __restrict__ Vh,
    __half* __restrict__ Oh, int b)
{
    extern __shared__ __align__(128) char smc[];
    const uint32_t smb = smem_u32(smc);
    const int tid = threadIdx.x;
    const int wid = tid >> 5;
    const int lane = tid & 31;
    const int bx = blockIdx.x;
    const int h = blockIdx.y;
    const size_t rc0 = (size_t)b * SEQ * D_MODEL + h * HDIM;

    const int wr = wid * 16;
    const uint32_t lrow = lane & 15;
    const uint32_t lc16 = (lane >> 4) * 16;

    auto load_q = [&](int q0) {
#pragma unroll
        for (int it = 0; it < 4; it++) {
            int idx = tid + it * 256;
            int r = idx >> 3, u = idx & 7;
            CP16(smb + (uint32_t)(r * ALD + u * 8) * 2,
                 Qhp + rc0 + (size_t)(q0 + r) * D_MODEL + u * 8);
        }
    };
    auto load_kv = [&](int kt, int stg) {
        const uint32_t sb = smb + AQ_B + stg * AST_B;
#pragma unroll
        for (int it = 0; it < 4; it++) {
            int t = tid + it * 256;
            int mtx = t >> 9;                   // 0:Kh 1:Vh
            int idx = t & 511, r = idx >> 3, u = idx & 7;
            const __half* src = (mtx == 0) ? Kh : Vh;
            CP16(sb + mtx * AM_B + (uint32_t)(r * ALD + u * 8) * 2,
                 src + rc0 + (size_t)(kt * 64 + r) * D_MODEL + u * 8);
        }
    };

    for (int half = 0; half < 2; half++) {
        const int qt = half ? (7 - bx) : (8 + bx);
        const int q0 = qt * 128;
        const int ktEnd = 2 * qt + 2;
        const int ktMaxW = (q0 + wr + 15) >> 6;   // last tile this warp needs

        float o[8][4];
#pragma unroll
        for (int nt = 0; nt < 8; nt++)
#pragma unroll
            for (int c = 0; c < 4; c++) o[nt][c] = 0.0f;
        float m0 = -1e30f, m1 = -1e30f, l0 = 0.0f, l1 = 0.0f;
        uint32_t qh[4][4];

        load_q(q0);
        load_kv(0, 0);
        CP_COMMIT();
        if (1 < ktEnd) load_kv(1, 1);
        CP_COMMIT();

        for (int kt = 0; kt < ktEnd; kt++) {
            CP_WAIT(1);
            __syncthreads();
            if (kt + 2 < ktEnd) load_kv(kt + 2, (kt + 2) % 3);
            CP_COMMIT();

            if (kt == 0) {
#pragma unroll
                for (int ks = 0; ks < 4; ks++) {
                    uint32_t a1 = smb + (uint32_t)((wr + lrow) * ALD) * 2 + ks * 32 + lc16;
                    LDSM4(qh[ks][0], qh[ks][1], qh[ks][2], qh[ks][3], a1);
                }
            }

            if (kt > ktMaxW) continue;   // fully masked for this warp's rows

            const uint32_t sb = smb + AQ_B + (kt % 3) * AST_B;

            // ---- S = Q K^T (single term) ----
            float s[8][4];
#pragma unroll
            for (int nt = 0; nt < 8; nt++)
#pragma unroll
                for (int c = 0; c < 4; c++) s[nt][c] = 0.0f;

#pragma unroll
            for (int ks = 0; ks < 4; ks++) {
                uint32_t kf[4][4];
#pragma unroll
                for (int ng = 0; ng < 4; ng++) {
                    uint32_t a1 = sb + (uint32_t)((ng * 16 + lrow) * ALD) * 2 + ks * 32 + lc16;
                    LDSM4(kf[ng][0], kf[ng][1], kf[ng][2], kf[ng][3], a1);
                }
#pragma unroll
                for (int nt = 0; nt < 8; nt++)
                    MMA_F16(s[nt], qh[ks], kf[nt >> 1][nt & 1], kf[nt >> 1][(nt & 1) + 2]);
            }

#pragma unroll
            for (int nt = 0; nt < 8; nt++)
#pragma unroll
                for (int c = 0; c < 4; c++) s[nt][c] *= SCL;   // log2-domain

            // ---- causal mask (diagonal tiles only) ----
            if (kt * 64 + 63 > q0 + wr) {
                const int r0 = q0 + wr + (lane >> 2);
#pragma unroll
                for (int nt = 0; nt < 8; nt++) {
                    const int c0 = kt * 64 + nt * 8 + 2 * (lane & 3);
                    if (c0 > r0)         s[nt][0] = -1e30f;
                    if (c0 + 1 > r0)     s[nt][1] = -1e30f;
                    if (c0 > r0 + 8)     s[nt][2] = -1e30f;
                    if (c0 + 1 > r0 + 8) s[nt][3] = -1e30f;
                }
            }

            // ---- online softmax (base-2, quad shuffles) ----
            float mx0 = -1e30f, mx1 = -1e30f;
#pragma unroll
            for (int nt = 0; nt < 8; nt++) {
                mx0 = fmaxf(mx0, fmaxf(s[nt][0], s[nt][1]));
                mx1 = fmaxf(mx1, fmaxf(s[nt][2], s[nt][3]));
            }
            mx0 = fmaxf(mx0, __shfl_xor_sync(0xffffffffu, mx0, 1));
            mx0 = fmaxf(mx0, __shfl_xor_sync(0xffffffffu, mx0, 2));
            mx1 = fmaxf(mx1, __shfl_xor_sync(0xffffffffu, mx1, 1));
            mx1 = fmaxf(mx1, __shfl_xor_sync(0xffffffffu, mx1, 2));
            const float n0 = fmaxf(m0, mx0), n1 = fmaxf(m1, mx1);
            const float cr0 = exp2f(m0 - n0), cr1 = exp2f(m1 - n1);
            m0 = n0; m1 = n1;
            float sum0 = 0.0f, sum1 = 0.0f;
#pragma unroll
            for (int nt = 0; nt < 8; nt++) {
                s[nt][0] = exp2f(s[nt][0] - n0); sum0 += s[nt][0];
                s[nt][1] = exp2f(s[nt][1] - n0); sum0 += s[nt][1];
                s[nt][2] = exp2f(s[nt][2] - n1); sum1 += s[nt][2];
                s[nt][3] = exp2f(s[nt][3] - n1); sum1 += s[nt][3];
            }
            sum0 += __shfl_xor_sync(0xffffffffu, sum0, 1);
            sum0 += __shfl_xor_sync(0xffffffffu, sum0, 2);
            sum1 += __shfl_xor_sync(0xffffffffu, sum1, 1);
            sum1 += __shfl_xor_sync(0xffffffffu, sum1, 2);
            l0 = l0 * cr0 + sum0;
            l1 = l1 * cr1 + sum1;
#pragma unroll
            for (int nt = 0; nt < 8; nt++) {
                o[nt][0] *= cr0; o[nt][1] *= cr0;
                o[nt][2] *= cr1; o[nt][3] *= cr1;
            }

            // ---- P fragments: single fp16 ----
            uint32_t ph[4][4];
#pragma unroll
            for (int ks = 0; ks < 4; ks++) {
                ph[ks][0] = pack2h(s[2 * ks][0], s[2 * ks][1]);
                ph[ks][1] = pack2h(s[2 * ks][2], s[2 * ks][3]);
                ph[ks][2] = pack2h(s[2 * ks + 1][0], s[2 * ks + 1][1]);
                ph[ks][3] = pack2h(s[2 * ks + 1][2], s[2 * ks + 1][3]);
            }

            // ---- O += P V (1 term) ----
#pragma unroll
            for (int ks = 0; ks < 4; ks++) {
                uint32_t vh[4][4];
#pragma unroll
                for (int ng = 0; ng < 4; ng++) {
                    uint32_t a1 = sb + AM_B + (uint32_t)((ks * 16 + lrow) * ALD) * 2 + ng * 32 + lc16;
                    LDSM4T(vh[ng][0], vh[ng][1], vh[ng][2], vh[ng][3], a1);
                }
#pragma unroll
                for (int nt = 0; nt < 8; nt++)
                    MMA_F16(o[nt], ph[ks], vh[nt >> 1][(nt & 1) * 2], vh[nt >> 1][(nt & 1) * 2 + 1]);
            }
        }

        // ---- epilogue: normalize, fp16 store ----
        const float i0 = 1.0f / l0, i1 = 1.0f / l1;
        const size_t r0 = (size_t)(b * SEQ + q0 + wr + (lane >> 2));
        const int colb = h * HDIM + 2 * (lane & 3);
#pragma unroll
        for (int nt = 0; nt < 8; nt++) {
            const int col = colb + nt * 8;
            *(uint32_t*)(Oh + r0 * D_MODEL + col) = pack2h(o[nt][0] * i0, o[nt][1] * i0);
            *(uint32_t*)(Oh + (r0 + 8) * D_MODEL + col) = pack2h(o[nt][2] * i1, o[nt][3] * i1);
        }

        // drain before next tile reuses Q/KV smem
        CP_WAIT(0);
        __syncthreads();
    }
}

// ---------------------------------------------------------------------------
// Launch: round-14 two-stream batch split + prepB on side stream.
// ---------------------------------------------------------------------------
extern "C" void kernel_launch(void* const* d_in, const int* in_sizes, int n_in,
                              void* d_out, int out_size)
{
    (void)in_sizes; (void)n_in; (void)out_size;
    const float* x  = (const float*)d_in[0];
    const float* Wq = (const float*)d_in[1];
    const float* bq = (const float*)d_in[2];
    const float* Wk = (const float*)d_in[3];
    const float* bk = (const float*)d_in[4];
    const float* Wv = (const float*)d_in[5];
    const float* bv = (const float*)d_in[6];
    const float* Wo = (const float*)d_in[7];
    const float* bo = (const float*)d_in[8];
    float* out = (float*)d_out;

    __half *xh, *wh, *qh, *kh, *vh, *oh;
    cudaGetSymbolAddress((void**)&xh, g_xh);
    cudaGetSymbolAddress((void**)&wh, g_wh);
    cudaGetSymbolAddress((void**)&qh, g_qh);
    cudaGetSymbolAddress((void**)&kh, g_kh);
    cudaGetSymbolAddress((void**)&vh, g_vh);
    cudaGetSymbolAddress((void**)&oh, g_oh);

    cudaFuncSetAttribute(attn_mma,
                         cudaFuncAttributeMaxDynamicSharedMemorySize, ATTN_SMEM);
    cudaFuncSetAttribute(gemm_qkv,
                         cudaFuncAttributeMaxDynamicSharedMemorySize, GEMM_SMEM);
    cudaFuncSetAttribute(gemm_out,
                         cudaFuncAttributeMaxDynamicSharedMemorySize, GEMM_SMEM);

    // One-time stream/event creation (first call = correctness run, not
    // under capture; later captures reuse them via fork/join events).
    static cudaStream_t s1 = nullptr, s2 = nullptr;
    static cudaEvent_t eStart = nullptr, eFork = nullptr, eWo = nullptr, eJoin = nullptr;
    static bool init_ok = false;
    if (!init_ok) {
        bool ok = true;
        ok = ok && (cudaStreamCreateWithFlags(&s1, cudaStreamNonBlocking) == cudaSuccess);
        ok = ok && (cudaStreamCreateWithFlags(&s2, cudaStreamNonBlocking) == cudaSuccess);
        ok = ok && (cudaEventCreateWithFlags(&eStart, cudaEventDisableTiming) == cudaSuccess);
        ok = ok && (cudaEventCreateWithFlags(&eFork, cudaEventDisableTiming) == cudaSuccess);
        ok = ok && (cudaEventCreateWithFlags(&eWo, cudaEventDisableTiming) == cudaSuccess);
        ok = ok && (cudaEventCreateWithFlags(&eJoin, cudaEventDisableTiming) == cudaSuccess);
        init_ok = ok;
        if (!ok) { s1 = s2 = nullptr; }
    }

    const __half* whO = wh + (size_t)3 * WN;
    const dim3 gQKV(3 * D_MODEL / 128, SEQ / 128);   // (24, 16) per batch
    const dim3 gAttn(SEQ / 256, NHEAD);              // (8, 16) per batch
    const dim3 gOut(D_MODEL / 128, SEQ / 128);       // (8, 16) per batch

    if (s1) {
        // fork prepB immediately (independent of prepA)
        cudaEventRecord(eStart, 0);
        cudaStreamWaitEvent(s2, eStart, 0);
        prepB_kernel<<<PREPB_BLOCKS, 256, 0, s2>>>(Wo, (__half*)whO);
        cudaEventRecord(eWo, s2);

        prepA_kernel<<<PREPA_BLOCKS, 256>>>(x, Wq, Wk, Wv, xh, wh);
        cudaEventRecord(eFork, 0);
        cudaStreamWaitEvent(s1, eFork, 0);

        // batch 0 on capture (default) stream
        gemm_qkv<<<gQKV, 256, GEMM_SMEM>>>(xh, wh, bq, bk, bv, qh, kh, vh, 0);
        attn_mma<<<gAttn, 256, ATTN_SMEM>>>(qh, kh, vh, oh, 0);
        cudaStreamWaitEvent(0, eWo, 0);
        gemm_out<<<gOut, 256, GEMM_SMEM>>>(oh, whO, bo, out, 0);

        // batch 1 on side stream
        gemm_qkv<<<gQKV, 256, GEMM_SMEM, s1>>>(xh, wh, bq, bk, bv, qh, kh, vh, SEQ);
        attn_mma<<<gAttn, 256, ATTN_SMEM, s1>>>(qh, kh, vh, oh, 1);
        cudaStreamWaitEvent(s1, eWo, 0);
        gemm_out<<<gOut, 256, GEMM_SMEM, s1>>>(oh, whO, bo, out, SEQ);

        // join
        cudaEventRecord(eJoin, s1);
        cudaStreamWaitEvent(0, eJoin, 0);
    } else {
        // fallback: serial on default stream
        prepA_kernel<<<PREPA_BLOCKS, 256>>>(x, Wq, Wk, Wv, xh, wh);
        prepB_kernel<<<PREPB_BLOCKS, 256>>>(Wo, (__half*)whO);
        gemm_qkv<<<gQKV, 256, GEMM_SMEM>>>(xh, wh, bq, bk, bv, qh, kh, vh, 0);
        gemm_qkv<<<gQKV, 256, GEMM_SMEM>>>(xh, wh, bq, bk, bv, qh, kh, vh, SEQ);
        attn_mma<<<gAttn, 256, ATTN_SMEM>>>(qh, kh, vh, oh, 0);
        attn_mma<<<gAttn, 256, ATTN_SMEM>>>(qh, kh, vh, oh, 1);
        gemm_out<<<gOut, 256, GEMM_SMEM>>>(oh, whO, bo, out, 0);
        gemm_out<<<gOut, 256, GEMM_SMEM>>>(oh, whO, bo, out, SEQ);
    }
}

// round 17
// speedup vs baseline: 1.0539x; 1.0266x over previous
#include <cuda_runtime.h>
#include <cuda_fp16.h>
#include <cstdint>
#include <cstddef>

#define D_MODEL 1024
#define SEQ     2048
#define BATCH   2
#define NHEAD   16
#define HDIM    64
#define MTOT    (BATCH * SEQ)          // 4096 rows

// ---------------------------------------------------------------------------
// Scratch (no cudaMalloc allowed) — all single fp16
// ---------------------------------------------------------------------------
__device__ __half g_xh[MTOT * D_MODEL];
__device__ __half g_wh[4 * D_MODEL * D_MODEL];   // Wq|Wk|Wv|Wo rows contiguous
__device__ __half g_qh[MTOT * D_MODEL];
__device__ __half g_kh[MTOT * D_MODEL];
__device__ __half g_vh[MTOT * D_MODEL];
__device__ __half g_oh[MTOT * D_MODEL];

// ---------------------------------------------------------------------------
// PTX helpers (sm_100-safe)
// ---------------------------------------------------------------------------
__device__ __forceinline__ uint32_t smem_u32(const void* p) {
    uint32_t a;
    asm("{ .reg .u64 t; cvta.to.shared.u64 t, %1; cvt.u32.u64 %0, t; }" : "=r"(a) : "l"(p));
    return a;
}
#define CP16(dst, src) \
    asm volatile("cp.async.cg.shared.global [%0], [%1], 16;" :: "r"(dst), "l"(src))
#define CP_COMMIT() asm volatile("cp.async.commit_group;" ::: "memory")
#define CP_WAIT(n)  asm volatile("cp.async.wait_group %0;" :: "n"(n) : "memory")

#define LDSM4(r0, r1, r2, r3, addr) \
    asm volatile("ldmatrix.sync.aligned.m8n8.x4.shared.b16 {%0,%1,%2,%3}, [%4];" \
                 : "=r"(r0), "=r"(r1), "=r"(r2), "=r"(r3) : "r"(addr))
#define LDSM4T(r0, r1, r2, r3, addr) \
    asm volatile("ldmatrix.sync.aligned.m8n8.x4.trans.shared.b16 {%0,%1,%2,%3}, [%4];" \
                 : "=r"(r0), "=r"(r1), "=r"(r2), "=r"(r3) : "r"(addr))

#define MMA_F16(d, a, b0, b1) \
    asm volatile("mma.sync.aligned.m16n8k16.row.col.f32.f16.f16.f32 " \
                 "{%0,%1,%2,%3}, {%4,%5,%6,%7}, {%8,%9}, {%0,%1,%2,%3};" \
                 : "+f"((d)[0]), "+f"((d)[1]), "+f"((d)[2]), "+f"((d)[3]) \
                 : "r"((a)[0]), "r"((a)[1]), "r"((a)[2]), "r"((a)[3]), \
                   "r"(b0), "r"(b1))

__device__ __forceinline__ uint32_t pack2h(float a, float b) {
    __half2 h = __floats2half2_rn(a, b);
    return *(uint32_t*)&h;
}

#define SCL 0.18033688f                // 0.125 * log2(e), folded into Q

// ---------------------------------------------------------------------------
// Preprocessing: prepA = x + Wq/Wk/Wv (feeds qkv); prepB = Wo (feeds out).
// ---------------------------------------------------------------------------
#define N4X (MTOT * D_MODEL / 4)       // 1048576
#define N4W (D_MODEL * D_MODEL / 4)    // 262144 = 1<<18
#define WN  (D_MODEL * D_MODEL)
#define NPREPA (N4X + 3 * N4W)         // 1835008
#define PREPA_BLOCKS (NPREPA / (256 * 4))  // 1792
#define PREPB_BLOCKS (N4W / (256 * 4))     // 256

__global__ __launch_bounds__(256) void prepA_kernel(
    const float* __restrict__ x,
    const float* __restrict__ Wq, const float* __restrict__ Wk,
    const float* __restrict__ Wv,
    __half* __restrict__ xh, __half* __restrict__ wh)
{
    const int stride = PREPA_BLOCKS * 256;
#pragma unroll
    for (int rep = 0; rep < 4; rep++) {
        int i = blockIdx.x * 256 + threadIdx.x + rep * stride;
        const float* src;
        __half2* dst;
        int w;
        if (i < N4X) {
            src = x; dst = (__half2*)xh; w = i;
        } else {
            int t = i - N4X;
            int j = t >> 18;
            w = t & (N4W - 1);
            src = (j == 0) ? Wq : (j == 1) ? Wk : Wv;
            dst = (__half2*)(wh + (size_t)j * WN);
        }
        float4 v = ((const float4*)src)[w];
        dst[2 * w] = __floats2half2_rn(v.x, v.y);
        dst[2 * w + 1] = __floats2half2_rn(v.z, v.w);
    }
}

__global__ __launch_bounds__(256) void prepB_kernel(
    const float* __restrict__ Wo, __half* __restrict__ whO)
{
    const int stride = PREPB_BLOCKS * 256;
#pragma unroll
    for (int rep = 0; rep < 4; rep++) {
        int w = blockIdx.x * 256 + threadIdx.x + rep * stride;
        float4 v = ((const float4*)Wo)[w];
        __half2* dst = (__half2*)whO;
        dst[2 * w] = __floats2half2_rn(v.x, v.y);
        dst[2 * w + 1] = __floats2half2_rn(v.z, v.w);
    }
}

// ---------------------------------------------------------------------------
// GEMM core: 128x128 C tile, BK=64 chunks, K=1024 -> 16 chunks, single fp16.
// 3-stage cp.async ring, ONE __syncthreads per chunk. Hoisted addresses.
// ---------------------------------------------------------------------------
#define GK 1024
#define GLD 72                          // row stride in fp16 (144 B, conflict-free)
#define GTB  (128 * GLD * 2)            // 18432 B per matrix tile
#define GSTB (2 * GTB)                  // 36864 B per stage (A + B)
#define GEMM_SMEM (3 * GSTB)            // 110592 B -> 2 CTAs/SM
#define NCH 16

struct GemmCore {
    uint32_t smb;
    int lane, wr, wc;
    uint32_t dstA[4];
    uint32_t offA[4], offW[4];
    uint32_t aRow[4], bRow[2];
    float acc[4][4][4];

    __device__ __forceinline__ void init(uint32_t smb_, int tid, int bm, int bn) {
        smb = smb_;
        const int wid = tid >> 5;
        lane = tid & 31;
        wr = (wid & 1) * 64; wc = (wid >> 1) * 32;
#pragma unroll
        for (int it = 0; it < 4; it++) {
            int idx = tid + it * 256;
            int r = idx >> 3, u = idx & 7;
            dstA[it] = (uint32_t)(r * GLD) * 2 + u * 16;
            offA[it] = (uint32_t)(bm + r) * GK + u * 8;
            offW[it] = (uint32_t)(bn + r) * GK + u * 8;
        }
#pragma unroll
        for (int mt = 0; mt < 4; mt++)
            aRow[mt] = (uint32_t)((wr + mt * 16 + (lane & 15)) * GLD) * 2 + (lane >> 4) * 16;
#pragma unroll
        for (int ng = 0; ng < 2; ng++)
            bRow[ng] = GTB + (uint32_t)((wc + ng * 16 + (lane & 15)) * GLD) * 2 + (lane >> 4) * 16;
#pragma unroll
        for (int mt = 0; mt < 4; mt++)
#pragma unroll
            for (int j = 0; j < 4; j++)
#pragma unroll
                for (int r = 0; r < 4; r++) acc[mt][j][r] = 0.0f;
    }
    __device__ __forceinline__ void load_chunk(
        const __half* __restrict__ A, const __half* __restrict__ W,
        int c, int stg) {
        const __half* Ap = A + c * 64;
        const __half* Wp = W + c * 64;
        const uint32_t sa = smb + stg * GSTB;
#pragma unroll
        for (int it = 0; it < 4; it++)
            CP16(sa + dstA[it], Ap + offA[it]);
#pragma unroll
        for (int it = 0; it < 4; it++)
            CP16(sa + GTB + dstA[it], Wp + offW[it]);
    }
    __device__ __forceinline__ void compute(int stg) {
        const uint32_t sa = smb + stg * GSTB;
#pragma unroll
        for (int ks = 0; ks < 4; ks++) {
            const uint32_t colb = ks * 32;
            uint32_t a[4][4], b[2][4];
#pragma unroll
            for (int mt = 0; mt < 4; mt++)
                LDSM4(a[mt][0], a[mt][1], a[mt][2], a[mt][3], sa + aRow[mt] + colb);
#pragma unroll
            for (int ng = 0; ng < 2; ng++)
                LDSM4(b[ng][0], b[ng][1], b[ng][2], b[ng][3], sa + bRow[ng] + colb);
#pragma unroll
            for (int mt = 0; mt < 4; mt++)
#pragma unroll
                for (int j = 0; j < 4; j++)
                    MMA_F16(acc[mt][j], a[mt], b[j >> 1][j & 1], b[j >> 1][(j & 1) + 2]);
        }
    }
    __device__ __forceinline__ void run(
        const __half* __restrict__ A, const __half* __restrict__ W) {
        load_chunk(A, W, 0, 0); CP_COMMIT();
        load_chunk(A, W, 1, 1); CP_COMMIT();
        for (int c = 0; c < NCH; c++) {
            CP_WAIT(1);
            __syncthreads();
            if (c + 2 < NCH) load_chunk(A, W, c + 2, (c + 2) % 3);
            CP_COMMIT();
            compute(c % 3);
        }
    }
};

// ---------------------------------------------------------------------------
// Fused QKV GEMM (per batch): N=3072 over contiguous Wq|Wk|Wv. 384 CTAs.
// Q output pre-scaled by SCL (softmax scale folded in).
// ---------------------------------------------------------------------------
__global__ __launch_bounds__(256, 2) void gemm_qkv(
    const __half* __restrict__ A, const __half* __restrict__ W,
    const float* __restrict__ bq, const float* __restrict__ bk,
    const float* __restrict__ bv,
    __half* __restrict__ Qh, __half* __restrict__ Kh, __half* __restrict__ Vh,
    int bm0)
{
    extern __shared__ __align__(128) char smg[];
    const int bn = blockIdx.x * 128;            // 0..2944
    const int bm = bm0 + blockIdx.y * 128;
    GemmCore g;
    g.init(smem_u32(smg), threadIdx.x, bm, bn);
    g.run(A, W);

    const int bh = bn >> 10;                    // 0:Q 1:K 2:V
    const int cb = bn & 1023;
    const float* bias = (bh == 0) ? bq : (bh == 1) ? bk : bv;
    __half* dst = (bh == 0) ? Qh : (bh == 1) ? Kh : Vh;
    const float scl = (bh == 0) ? SCL : 1.0f;
    const int rq = g.lane >> 2;
    const int cq = (g.lane & 3) * 2;
#pragma unroll
    for (int mt = 0; mt < 4; mt++) {
#pragma unroll
        for (int j = 0; j < 4; j++) {
            const int col = cb + g.wc + j * 8 + cq;
            const float b0 = bias[col], b1 = bias[col + 1];
            const int row0 = bm + g.wr + mt * 16 + rq;
            *(__half2*)(dst + (size_t)row0 * D_MODEL + col) =
                __floats2half2_rn((g.acc[mt][j][0] + b0) * scl,
                                  (g.acc[mt][j][1] + b1) * scl);
            *(__half2*)(dst + (size_t)(row0 + 8) * D_MODEL + col) =
                __floats2half2_rn((g.acc[mt][j][2] + b0) * scl,
                                  (g.acc[mt][j][3] + b1) * scl);
        }
    }
}

// ---------------------------------------------------------------------------
// Output projection GEMM (per batch): fp32 out + bias, N=1024.
// ---------------------------------------------------------------------------
__global__ __launch_bounds__(256, 2) void gemm_out(
    const __half* __restrict__ A, const __half* __restrict__ W,
    const float* __restrict__ bias, float* __restrict__ C, int bm0)
{
    extern __shared__ __align__(128) char smg[];
    const int bn = blockIdx.x * 128;
    const int bm = bm0 + blockIdx.y * 128;
    GemmCore g;
    g.init(smem_u32(smg), threadIdx.x, bm, bn);
    g.run(A, W);

    const int rq = g.lane >> 2;
    const int cq = (g.lane & 3) * 2;
#pragma unroll
    for (int mt = 0; mt < 4; mt++) {
#pragma unroll
        for (int j = 0; j < 4; j++) {
            const int col = bn + g.wc + j * 8 + cq;
            const float b0 = bias[col], b1 = bias[col + 1];
            const int row0 = bm + g.wr + mt * 16 + rq;
            *(float2*)(C + (size_t)row0 * D_MODEL + col) =
                make_float2(g.acc[mt][j][0] + b0, g.acc[mt][j][1] + b1);
            *(float2*)(C + (size_t)(row0 + 8) * D_MODEL + col) =
                make_float2(g.acc[mt][j][2] + b0, g.acc[mt][j][3] + b1);
        }
    }
}

// ---------------------------------------------------------------------------
// Flash attention (per batch, all 16 heads). Paired Q tiles, 3-stage KV ring.
// Q arrives pre-scaled by SCL -> scores are directly log2-domain.
// ---------------------------------------------------------------------------
#define ALD 72
#define AQ_B  (128 * ALD * 2)
#define AM_B  (64 * ALD * 2)
#define AST_B (2 * AM_B)
#define ATTN_SMEM (AQ_B + 3 * AST_B)   // 73728 B -> 2 CTAs/SM

__global__ __launch_bounds__(256, 2) void attn_mma(
    const __half* __restrict__ Qhp,
    const __half* __restrict__ Kh, const __half* __restrict__ Vh,
    __half* __restrict__ Oh, int b)
{
    extern __shared__ __align__(128) char smc[];
    const uint32_t smb = smem_u32(smc);
    const int tid = threadIdx.x;
    const int wid = tid >> 5;
    const int lane = tid & 31;
    const int bx = blockIdx.x;
    const int h = blockIdx.y;
    const size_t rc0 = (size_t)b * SEQ * D_MODEL + h * HDIM;

    const int wr = wid * 16;
    const uint32_t lrow = lane & 15;
    const uint32_t lc16 = (lane >> 4) * 16;

    auto load_q = [&](int q0) {
#pragma unroll
        for (int it = 0; it < 4; it++) {
            int idx = tid + it * 256;
            int r = idx >> 3, u = idx & 7;
            CP16(smb + (uint32_t)(r * ALD + u * 8) * 2,
                 Qhp + rc0 + (size_t)(q0 + r) * D_MODEL + u * 8);
        }
    };
    auto load_kv = [&](int kt, int stg) {
        const uint32_t sb = smb + AQ_B + stg * AST_B;
#pragma unroll
        for (int it = 0; it < 4; it++) {
            int t = tid + it * 256;
            int mtx = t >> 9;                   // 0:Kh 1:Vh
            int idx = t & 511, r = idx >> 3, u = idx & 7;
            const __half* src = (mtx == 0) ? Kh : Vh;
            CP16(sb + mtx * AM_B + (uint32_t)(r * ALD + u * 8) * 2,
                 src + rc0 + (size_t)(kt * 64 + r) * D_MODEL + u * 8);
        }
    };

    for (int half = 0; half < 2; half++) {
        const int qt = half ? (7 - bx) : (8 + bx);
        const int q0 = qt * 128;
        const int ktEnd = 2 * qt + 2;

        float o[8][4];
#pragma unroll
        for (int nt = 0; nt < 8; nt++)
#pragma unroll
            for (int c = 0; c < 4; c++) o[nt][c] = 0.0f;
        float m0 = -1e30f, m1 = -1e30f, l0 = 0.0f, l1 = 0.0f;
        uint32_t qh[4][4];

        load_q(q0);
        load_kv(0, 0);
        CP_COMMIT();
        if (1 < ktEnd) load_kv(1, 1);
        CP_COMMIT();

        for (int kt = 0; kt < ktEnd; kt++) {
            CP_WAIT(1);
            __syncthreads();
            if (kt + 2 < ktEnd) load_kv(kt + 2, (kt + 2) % 3);
            CP_COMMIT();

            if (kt == 0) {
#pragma unroll
                for (int ks = 0; ks < 4; ks++) {
                    uint32_t a1 = smb + (uint32_t)((wr + lrow) * ALD) * 2 + ks * 32 + lc16;
                    LDSM4(qh[ks][0], qh[ks][1], qh[ks][2], qh[ks][3], a1);
                }
            }

            const uint32_t sb = smb + AQ_B + (kt % 3) * AST_B;

            // ---- S = Q K^T (Q pre-scaled: S already log2-domain) ----
            float s[8][4];
#pragma unroll
            for (int nt = 0; nt < 8; nt++)
#pragma unroll
                for (int c = 0; c < 4; c++) s[nt][c] = 0.0f;

#pragma unroll
            for (int ks = 0; ks < 4; ks++) {
                uint32_t kf[4][4];
#pragma unroll
                for (int ng = 0; ng < 4; ng++) {
                    uint32_t a1 = sb + (uint32_t)((ng * 16 + lrow) * ALD) * 2 + ks * 32 + lc16;
                    LDSM4(kf[ng][0], kf[ng][1], kf[ng][2], kf[ng][3], a1);
                }
#pragma unroll
                for (int nt = 0; nt < 8; nt++)
                    MMA_F16(s[nt], qh[ks], kf[nt >> 1][nt & 1], kf[nt >> 1][(nt & 1) + 2]);
            }

            // ---- causal mask (diagonal tiles only) ----
            if (kt * 64 + 63 > q0 + wr) {
                const int r0 = q0 + wr + (lane >> 2);
#pragma unroll
                for (int nt = 0; nt < 8; nt++) {
                    const int c0 = kt * 64 + nt * 8 + 2 * (lane & 3);
                    if (c0 > r0)         s[nt][0] = -1e30f;
                    if (c0 + 1 > r0)     s[nt][1] = -1e30f;
                    if (c0 > r0 + 8)     s[nt][2] = -1e30f;
                    if (c0 + 1 > r0 + 8) s[nt][3] = -1e30f;
                }
            }

            // ---- online softmax (base-2, quad shuffles) ----
            float mx0 = -1e30f, mx1 = -1e30f;
#pragma unroll
            for (int nt = 0; nt < 8; nt++) {
                mx0 = fmaxf(mx0, fmaxf(s[nt][0], s[nt][1]));
                mx1 = fmaxf(mx1, fmaxf(s[nt][2], s[nt][3]));
            }
            mx0 = fmaxf(mx0, __shfl_xor_sync(0xffffffffu, mx0, 1));
            mx0 = fmaxf(mx0, __shfl_xor_sync(0xffffffffu, mx0, 2));
            mx1 = fmaxf(mx1, __shfl_xor_sync(0xffffffffu, mx1, 1));
            mx1 = fmaxf(mx1, __shfl_xor_sync(0xffffffffu, mx1, 2));
            const float n0 = fmaxf(m0, mx0), n1 = fmaxf(m1, mx1);
            const float cr0 = exp2f(m0 - n0), cr1 = exp2f(m1 - n1);
            m0 = n0; m1 = n1;
            float sum0 = 0.0f, sum1 = 0.0f;
#pragma unroll
            for (int nt = 0; nt < 8; nt++) {
                s[nt][0] = exp2f(s[nt][0] - n0); sum0 += s[nt][0];
                s[nt][1] = exp2f(s[nt][1] - n0); sum0 += s[nt][1];
                s[nt][2] = exp2f(s[nt][2] - n1); sum1 += s[nt][2];
                s[nt][3] = exp2f(s[nt][3] - n1); sum1 += s[nt][3];
            }
            sum0 += __shfl_xor_sync(0xffffffffu, sum0, 1);
            sum0 += __shfl_xor_sync(0xffffffffu, sum0, 2);
            sum1 += __shfl_xor_sync(0xffffffffu, sum1, 1);
            sum1 += __shfl_xor_sync(0xffffffffu, sum1, 2);
            l0 = l0 * cr0 + sum0;
            l1 = l1 * cr1 + sum1;
#pragma unroll
            for (int nt = 0; nt < 8; nt++) {
                o[nt][0] *= cr0; o[nt][1] *= cr0;
                o[nt][2] *= cr1; o[nt][3] *= cr1;
            }

            // ---- P fragments: single fp16 ----
            uint32_t ph[4][4];
#pragma unroll
            for (int ks = 0; ks < 4; ks++) {
                ph[ks][0] = pack2h(s[2 * ks][0], s[2 * ks][1]);
                ph[ks][1] = pack2h(s[2 * ks][2], s[2 * ks][3]);
                ph[ks][2] = pack2h(s[2 * ks + 1][0], s[2 * ks + 1][1]);
                ph[ks][3] = pack2h(s[2 * ks + 1][2], s[2 * ks + 1][3]);
            }

            // ---- O += P V (1 term) ----
#pragma unroll
            for (int ks = 0; ks < 4; ks++) {
                uint32_t vh[4][4];
#pragma unroll
                for (int ng = 0; ng < 4; ng++) {
                    uint32_t a1 = sb + AM_B + (uint32_t)((ks * 16 + lrow) * ALD) * 2 + ng * 32 + lc16;
                    LDSM4T(vh[ng][0], vh[ng][1], vh[ng][2], vh[ng][3], a1);
                }
#pragma unroll
                for (int nt = 0; nt < 8; nt++)
                    MMA_F16(o[nt], ph[ks], vh[nt >> 1][(nt & 1) * 2], vh[nt >> 1][(nt & 1) * 2 + 1]);
            }
        }

        // ---- epilogue: normalize, fp16 store ----
        const float i0 = 1.0f / l0, i1 = 1.0f / l1;
        const size_t r0 = (size_t)(b * SEQ + q0 + wr + (lane >> 2));
        const int colb = h * HDIM + 2 * (lane & 3);
#pragma unroll
        for (int nt = 0; nt < 8; nt++) {
            const int col = colb + nt * 8;
            *(uint32_t*)(Oh + r0 * D_MODEL + col) = pack2h(o[nt][0] * i0, o[nt][1] * i0);
            *(uint32_t*)(Oh + (r0 + 8) * D_MODEL + col) = pack2h(o[nt][2] * i1, o[nt][3] * i1);
        }

        // drain before next tile reuses Q/KV smem
        CP_WAIT(0);
        __syncthreads();
    }
}

// ---------------------------------------------------------------------------
// Launch: round-14 two-stream batch split + prepB on side stream.
// ---------------------------------------------------------------------------
extern "C" void kernel_launch(void* const* d_in, const int* in_sizes, int n_in,
                              void* d_out, int out_size)
{
    (void)in_sizes; (void)n_in; (void)out_size;
    const float* x  = (const float*)d_in[0];
    const float* Wq = (const float*)d_in[1];
    const float* bq = (const float*)d_in[2];
    const float* Wk = (const float*)d_in[3];
    const float* bk = (const float*)d_in[4];
    const float* Wv = (const float*)d_in[5];
    const float* bv = (const float*)d_in[6];
    const float* Wo = (const float*)d_in[7];
    const float* bo = (const float*)d_in[8];
    float* out = (float*)d_out;

    __half *xh, *wh, *qh, *kh, *vh, *oh;
    cudaGetSymbolAddress((void**)&xh, g_xh);
    cudaGetSymbolAddress((void**)&wh, g_wh);
    cudaGetSymbolAddress((void**)&qh, g_qh);
    cudaGetSymbolAddress((void**)&kh, g_kh);
    cudaGetSymbolAddress((void**)&vh, g_vh);
    cudaGetSymbolAddress((void**)&oh, g_oh);

    cudaFuncSetAttribute(attn_mma,
                         cudaFuncAttributeMaxDynamicSharedMemorySize, ATTN_SMEM);
    cudaFuncSetAttribute(gemm_qkv,
                         cudaFuncAttributeMaxDynamicSharedMemorySize, GEMM_SMEM);
    cudaFuncSetAttribute(gemm_out,
                         cudaFuncAttributeMaxDynamicSharedMemorySize, GEMM_SMEM);

    // One-time stream/event creation (first call = correctness run, not
    // under capture; later captures reuse them via fork/join events).
    static cudaStream_t s1 = nullptr, s2 = nullptr;
    static cudaEvent_t eStart = nullptr, eFork = nullptr, eWo = nullptr, eJoin = nullptr;
    static bool init_ok = false;
    if (!init_ok) {
        bool ok = true;
        ok = ok && (cudaStreamCreateWithFlags(&s1, cudaStreamNonBlocking) == cudaSuccess);
        ok = ok && (cudaStreamCreateWithFlags(&s2, cudaStreamNonBlocking) == cudaSuccess);
        ok = ok && (cudaEventCreateWithFlags(&eStart, cudaEventDisableTiming) == cudaSuccess);
        ok = ok && (cudaEventCreateWithFlags(&eFork, cudaEventDisableTiming) == cudaSuccess);
        ok = ok && (cudaEventCreateWithFlags(&eWo, cudaEventDisableTiming) == cudaSuccess);
        ok = ok && (cudaEventCreateWithFlags(&eJoin, cudaEventDisableTiming) == cudaSuccess);
        init_ok = ok;
        if (!ok) { s1 = s2 = nullptr; }
    }

    const __half* whO = wh + (size_t)3 * WN;
    const dim3 gQKV(3 * D_MODEL / 128, SEQ / 128);   // (24, 16) per batch
    const dim3 gAttn(SEQ / 256, NHEAD);              // (8, 16) per batch
    const dim3 gOut(D_MODEL / 128, SEQ / 128);       // (8, 16) per batch

    if (s1) {
        // fork prepB immediately (independent of prepA)
        cudaEventRecord(eStart, 0);
        cudaStreamWaitEvent(s2, eStart, 0);
        prepB_kernel<<<PREPB_BLOCKS, 256, 0, s2>>>(Wo, (__half*)whO);
        cudaEventRecord(eWo, s2);

        prepA_kernel<<<PREPA_BLOCKS, 256>>>(x, Wq, Wk, Wv, xh, wh);
        cudaEventRecord(eFork, 0);
        cudaStreamWaitEvent(s1, eFork, 0);

        // batch 0 on capture (default) stream
        gemm_qkv<<<gQKV, 256, GEMM_SMEM>>>(xh, wh, bq, bk, bv, qh, kh, vh, 0);
        attn_mma<<<gAttn, 256, ATTN_SMEM>>>(qh, kh, vh, oh, 0);
        cudaStreamWaitEvent(0, eWo, 0);
        gemm_out<<<gOut, 256, GEMM_SMEM>>>(oh, whO, bo, out, 0);

        // batch 1 on side stream
        gemm_qkv<<<gQKV, 256, GEMM_SMEM, s1>>>(xh, wh, bq, bk, bv, qh, kh, vh, SEQ);
        attn_mma<<<gAttn, 256, ATTN_SMEM, s1>>>(qh, kh, vh, oh, 1);
        cudaStreamWaitEvent(s1, eWo, 0);
        gemm_out<<<gOut, 256, GEMM_SMEM, s1>>>(oh, whO, bo, out, SEQ);

        // join
        cudaEventRecord(eJoin, s1);
        cudaStreamWaitEvent(0, eJoin, 0);
    } else {
        // fallback: serial on default stream
        prepA_kernel<<<PREPA_BLOCKS, 256>>>(x, Wq, Wk, Wv, xh, wh);
        prepB_kernel<<<PREPB_BLOCKS, 256>>>(Wo, (__half*)whO);
        gemm_qkv<<<gQKV, 256, GEMM_SMEM>>>(xh, wh, bq, bk, bv, qh, kh, vh, 0);
        gemm_qkv<<<gQKV, 256, GEMM_SMEM>>>(xh, wh, bq, bk, bv, qh, kh, vh, SEQ);
        attn_mma<<<gAttn, 256, ATTN_SMEM>>>(qh, kh, vh, oh, 0);
        attn_mma<<<gAttn, 256, ATTN_SMEM>>>(qh, kh, vh, oh, 1);
        gemm_out<<<gOut, 256, GEMM_SMEM>>>(oh, whO, bo, out, 0);
        gemm_out<<<gOut, 256, GEMM_SMEM>>>(oh, whO, bo, out, SEQ);
    }
}